// round 5
// baseline (speedup 1.0000x reference)
#include <cuda_runtime.h>
#include <cstdint>

// Embedding gather: out[i] = table[ids_flat[i]], D = 64 fp32 (256B/row).
// - 16 threads per row-chunk, one float4 per thread.
// - 8 independent gathers per thread (eighths of the index space), fully
//   front-batched: 8 id LDGs -> 8 table LDG.128s in flight -> 8 streaming
//   stores. Maximizes per-warp DRAM queue occupancy (MLP_p1=8).
// - __stcs output stores keep the table L2-resident (repeat ids hit L2).

__global__ void __launch_bounds__(256)
embed_gather_kernel(const int* __restrict__ ids,
                    const float4* __restrict__ table4,   // [VOCAB, 16] float4
                    float4* __restrict__ out4,           // [N, 16] float4
                    int n_rows, int vocab)
{
    long long total = (long long)n_rows * 16;            // total float4 chunks
    long long seg   = total >> 3;                        // n_rows % 8 == 0 here
    long long g     = (long long)blockIdx.x * blockDim.x + threadIdx.x;

    if (g < seg) {
        long long gi[8];
        #pragma unroll
        for (int k = 0; k < 8; k++) gi[k] = g + (long long)k * seg;

        // Batch id loads (8 independent LDG.32s).
        int id[8];
        #pragma unroll
        for (int k = 0; k < 8; k++) id[k] = __ldg(&ids[(int)(gi[k] >> 4)]);
        #pragma unroll
        for (int k = 0; k < 8; k++)
            if ((unsigned)id[k] >= (unsigned)vocab) id[k] = 0;

        // 8 independent gathers in flight (LDG.128 each).
        float4 v[8];
        #pragma unroll
        for (int k = 0; k < 8; k++)
            v[k] = __ldg(table4 + (long long)id[k] * 16 + (int)(gi[k] & 15));

        // Streaming stores: don't pollute L2.
        #pragma unroll
        for (int k = 0; k < 8; k++)
            __stcs(out4 + gi[k], v[k]);
    } else {
        // Tail for totals not divisible by 8 (not hit with these shapes).
        long long rem = 8 * seg + (g - seg);
        if (rem < total) {
            int row = (int)(rem >> 4), chunk = (int)(rem & 15);
            int idt = __ldg(&ids[row]);
            if ((unsigned)idt >= (unsigned)vocab) idt = 0;
            __stcs(out4 + rem, __ldg(table4 + (long long)idt * 16 + chunk));
        }
    }
}

extern "C" void kernel_launch(void* const* d_in, const int* in_sizes, int n_in,
                              void* d_out, int out_size)
{
    const int*    ids   = (const int*)d_in[0];
    const float4* table = (const float4*)d_in[1];
    float4*       out   = (float4*)d_out;

    int n_rows = in_sizes[0];                  // 819200
    int vocab  = in_sizes[1] / 64;             // 1,000,000

    long long total4   = (long long)n_rows * 16;     // 13,107,200
    long long seg      = total4 >> 3;
    long long tail     = total4 - 8 * seg;           // 0..7
    long long nthreads = seg + tail;

    int threads = 256;
    int blocks  = (int)((nthreads + threads - 1) / threads);
    embed_gather_kernel<<<blocks, threads>>>(ids, table, out, n_rows, vocab);
}

// round 6
// speedup vs baseline: 1.0343x; 1.0343x over previous
#include <cuda_runtime.h>
#include <cstdint>

// Embedding gather: out[i] = table[ids_flat[i]], D = 64 fp32 (256B/row).
// - 16 threads per row-chunk, one float4 per thread.
// - 4 independent gathers per thread (quarters of the index space),
//   front-batched: 4 id LDGs -> 4 table LDG.128s in flight -> 4 streaming
//   stores. MLP_p1=4 is the measured sweet spot (8 overflows the L1tex
//   wavefront queue; 2 under-fills DRAM queues).
// - __stcs output stores keep the table L2-resident (repeat ids hit L2).
// - 512-thread blocks: fewer resident CTAs/SM at equal warp count reduces
//   cross-CTA L1tex queue contention (spread-floor term).

__global__ void __launch_bounds__(512)
embed_gather_kernel(const int* __restrict__ ids,
                    const float4* __restrict__ table4,   // [VOCAB, 16] float4
                    float4* __restrict__ out4,           // [N, 16] float4
                    int n_rows, int vocab)
{
    long long total = (long long)n_rows * 16;            // total float4 chunks
    long long q     = total >> 2;                        // n_rows % 4 == 0 here
    long long g     = (long long)blockIdx.x * blockDim.x + threadIdx.x;

    if (g < q) {
        long long g0 = g, g1 = g + q, g2 = g + 2 * q, g3 = g + 3 * q;

        // Batch id loads (4 independent LDGs, broadcast within half-warp).
        int id0 = __ldg(&ids[(int)(g0 >> 4)]);
        int id1 = __ldg(&ids[(int)(g1 >> 4)]);
        int id2 = __ldg(&ids[(int)(g2 >> 4)]);
        int id3 = __ldg(&ids[(int)(g3 >> 4)]);
        if ((unsigned)id0 >= (unsigned)vocab) id0 = 0;
        if ((unsigned)id1 >= (unsigned)vocab) id1 = 0;
        if ((unsigned)id2 >= (unsigned)vocab) id2 = 0;
        if ((unsigned)id3 >= (unsigned)vocab) id3 = 0;

        int c0 = (int)(g0 & 15), c1 = (int)(g1 & 15);
        int c2 = (int)(g2 & 15), c3 = (int)(g3 & 15);

        // 4 independent gathers in flight.
        float4 v0 = __ldg(table4 + (long long)id0 * 16 + c0);
        float4 v1 = __ldg(table4 + (long long)id1 * 16 + c1);
        float4 v2 = __ldg(table4 + (long long)id2 * 16 + c2);
        float4 v3 = __ldg(table4 + (long long)id3 * 16 + c3);

        __stcs(out4 + g0, v0);      // streaming store: don't pollute L2
        __stcs(out4 + g1, v1);
        __stcs(out4 + g2, v2);
        __stcs(out4 + g3, v3);
    } else {
        // Tail for totals not divisible by 4 (not hit with these shapes).
        long long rem = 4 * q + (g - q);
        if (rem < total) {
            int row = (int)(rem >> 4), chunk = (int)(rem & 15);
            int id = __ldg(&ids[row]);
            if ((unsigned)id >= (unsigned)vocab) id = 0;
            __stcs(out4 + rem, __ldg(table4 + (long long)id * 16 + chunk));
        }
    }
}

extern "C" void kernel_launch(void* const* d_in, const int* in_sizes, int n_in,
                              void* d_out, int out_size)
{
    const int*    ids   = (const int*)d_in[0];
    const float4* table = (const float4*)d_in[1];
    float4*       out   = (float4*)d_out;

    int n_rows = in_sizes[0];                  // 819200
    int vocab  = in_sizes[1] / 64;             // 1,000,000

    long long total4   = (long long)n_rows * 16;     // 13,107,200
    long long q        = total4 >> 2;
    long long tail     = total4 - 4 * q;             // 0..3
    long long nthreads = q + tail;

    int threads = 512;
    int blocks  = (int)((nthreads + threads - 1) / threads);
    embed_gather_kernel<<<blocks, threads>>>(ids, table, out, n_rows, vocab);
}